// round 8
// baseline (speedup 1.0000x reference)
#include <cuda_runtime.h>
#include <cuda_fp16.h>
#include <cstdint>

#define N_USERS 100000
#define N_ITEMS 60000
#define N_NODES (N_USERS + N_ITEMS)
#define EMB_DIM 128
#define VEC (EMB_DIM / 4)        // 32 chunks/row: float4 (fp32) or uint2 (fp16x4)
#define N_EDGES 1500000

// Scratch (__device__ globals per allocation-free rule)
__device__ uint2 g_x0h[(size_t)N_NODES * VEC];
__device__ uint2 g_x1[(size_t)N_NODES * VEC];
__device__ uint2 g_x2[(size_t)N_NODES * VEC];
__device__ float g_invdeg[N_NODES];
__device__ int   g_deg[N_NODES];
__device__ int   g_rowptr[N_NODES];
__device__ int   g_cursor[N_NODES];
__device__ int   g_csr[N_EDGES];
__device__ int   g_counter[1];

// ---------------------------------------------------------------------------
__device__ __forceinline__ float4 h4_to_f4(uint2 u) {
    float2 lo = __half22float2(*reinterpret_cast<__half2*>(&u.x));
    float2 hi = __half22float2(*reinterpret_cast<__half2*>(&u.y));
    float4 r; r.x = lo.x; r.y = lo.y; r.z = hi.x; r.w = hi.y;
    return r;
}
__device__ __forceinline__ uint2 f4_to_h4(float4 v) {
    __half2 lo = __floats2half2_rn(v.x, v.y);
    __half2 hi = __floats2half2_rn(v.z, v.w);
    uint2 u;
    u.x = *reinterpret_cast<uint32_t*>(&lo);
    u.y = *reinterpret_cast<uint32_t*>(&hi);
    return u;
}
__device__ __forceinline__ void acc4(float4& a, float4 v) {
    a.x += v.x; a.y += v.y; a.z += v.z; a.w += v.w;
}

// 1) fused: convert concat(ue,ie) fp32->fp16 table  +  dst degree histogram
__global__ void convhist_kernel(const float4* __restrict__ ue,
                                const float4* __restrict__ ie,
                                uint2* __restrict__ x0h,
                                const int* __restrict__ dst,
                                int* __restrict__ deg) {
    long i = (long)blockIdx.x * blockDim.x + threadIdx.x;
    const long total = (long)N_NODES * VEC;        // 5,120,000
    if (i < total) {
        const long user_lim = (long)N_USERS * VEC;
        float4 v = (i < user_lim) ? __ldcs(&ue[i]) : __ldcs(&ie[i - user_lim]);
        __stcs(&x0h[i], f4_to_h4(v));
    }
    if (i < N_EDGES) atomicAdd(&deg[dst[(int)i]], 1);
}

// 2) segment assignment: rows live at arbitrary offsets handed out by a
//    global cursor (replaces the 3-kernel prefix scan). Also computes invdeg.
__global__ void assign_kernel(const int* __restrict__ deg,
                              int* __restrict__ rowptr,
                              int* __restrict__ cursor,
                              float* __restrict__ invdeg,
                              int* __restrict__ counter) {
    int v = blockIdx.x * blockDim.x + threadIdx.x;
    if (v >= N_NODES) return;
    int d = deg[v];
    int beg = (d > 0) ? atomicAdd(counter, d) : 0;
    rowptr[v] = beg;
    cursor[v] = beg;
    invdeg[v] = (d > 0) ? (1.0f / (float)d) : 0.0f;
}

// 3) bin edges by dst into the assigned segments
__global__ void permute_kernel(const int* __restrict__ src,
                               const int* __restrict__ dst,
                               int* __restrict__ cursor,
                               int* __restrict__ csr) {
    int e = blockIdx.x * blockDim.x + threadIdx.x;
    if (e < N_EDGES) {
        int pos = atomicAdd(&cursor[dst[e]], 1);
        csr[pos] = src[e];
    }
}

// ---------------------------------------------------------------------------
// Warp-per-node mean over an fp16 table; 8-deep unrolled gather.
__device__ __forceinline__ float4 row_mean_h(const int* __restrict__ rowptr,
                                             const int* __restrict__ deg,
                                             const int* __restrict__ csr,
                                             const float* __restrict__ invdeg,
                                             const uint2* __restrict__ xin,
                                             int w, int lane) {
    int beg = __ldg(&rowptr[w]);
    int end = beg + __ldg(&deg[w]);
    float4 a0 = {0,0,0,0}, a1 = {0,0,0,0}, a2 = {0,0,0,0}, a3 = {0,0,0,0};
    int i = beg;
    for (; i + 7 < end; i += 8) {
        int s0 = csr[i],   s1 = csr[i+1], s2 = csr[i+2], s3 = csr[i+3];
        int s4 = csr[i+4], s5 = csr[i+5], s6 = csr[i+6], s7 = csr[i+7];
        uint2 u0 = __ldg(&xin[(long)s0 * VEC + lane]);
        uint2 u1 = __ldg(&xin[(long)s1 * VEC + lane]);
        uint2 u2 = __ldg(&xin[(long)s2 * VEC + lane]);
        uint2 u3 = __ldg(&xin[(long)s3 * VEC + lane]);
        uint2 u4 = __ldg(&xin[(long)s4 * VEC + lane]);
        uint2 u5 = __ldg(&xin[(long)s5 * VEC + lane]);
        uint2 u6 = __ldg(&xin[(long)s6 * VEC + lane]);
        uint2 u7 = __ldg(&xin[(long)s7 * VEC + lane]);
        acc4(a0, h4_to_f4(u0)); acc4(a1, h4_to_f4(u1));
        acc4(a2, h4_to_f4(u2)); acc4(a3, h4_to_f4(u3));
        acc4(a0, h4_to_f4(u4)); acc4(a1, h4_to_f4(u5));
        acc4(a2, h4_to_f4(u6)); acc4(a3, h4_to_f4(u7));
    }
    for (; i + 3 < end; i += 4) {
        int s0 = csr[i], s1 = csr[i+1], s2 = csr[i+2], s3 = csr[i+3];
        uint2 u0 = __ldg(&xin[(long)s0 * VEC + lane]);
        uint2 u1 = __ldg(&xin[(long)s1 * VEC + lane]);
        uint2 u2 = __ldg(&xin[(long)s2 * VEC + lane]);
        uint2 u3 = __ldg(&xin[(long)s3 * VEC + lane]);
        acc4(a0, h4_to_f4(u0)); acc4(a1, h4_to_f4(u1));
        acc4(a2, h4_to_f4(u2)); acc4(a3, h4_to_f4(u3));
    }
    for (; i < end; ++i) {
        int s = csr[i];
        acc4(a0, h4_to_f4(__ldg(&xin[(long)s * VEC + lane])));
    }
    float sc = __ldg(&invdeg[w]);
    float4 r;
    r.x = (a0.x + a1.x + a2.x + a3.x) * sc;
    r.y = (a0.y + a1.y + a2.y + a3.y) * sc;
    r.z = (a0.z + a1.z + a2.z + a3.z) * sc;
    r.w = (a0.w + a1.w + a2.w + a3.w) * sc;
    return r;
}

// Layers 1 & 2: xout (fp16) = A~ @ xin (fp16). Plain store: xout is the next
// layer's gather table, keep it L2-resident (no .cs!).
__global__ void __launch_bounds__(256)
layer_kernel(const int* __restrict__ rowptr, const int* __restrict__ deg,
             const int* __restrict__ csr, const float* __restrict__ invdeg,
             const uint2* __restrict__ xin, uint2* __restrict__ xout) {
    int w = (blockIdx.x * blockDim.x + threadIdx.x) >> 5;
    int lane = threadIdx.x & 31;
    if (w >= N_NODES) return;
    float4 r = row_mean_h(rowptr, deg, csr, invdeg, xin, w, lane);
    xout[(long)w * VEC + lane] = f4_to_h4(r);
}

// Layer 3 fused finale: r = A~ @ x2 (regs only); out = 0.25*(x0_fp32+x1+x2+r)
__global__ void __launch_bounds__(256)
layer3_kernel(const int* __restrict__ rowptr, const int* __restrict__ deg,
              const int* __restrict__ csr, const float* __restrict__ invdeg,
              const float4* __restrict__ ue, const float4* __restrict__ ie,
              const uint2* __restrict__ x1, const uint2* __restrict__ x2,
              float4* __restrict__ out) {
    int w = (blockIdx.x * blockDim.x + threadIdx.x) >> 5;
    int lane = threadIdx.x & 31;
    if (w >= N_NODES) return;
    float4 r = row_mean_h(rowptr, deg, csr, invdeg, x2, w, lane);
    long o = (long)w * VEC + lane;
    float4 v0 = (w < N_USERS) ? __ldcs(&ue[o]) : __ldcs(&ie[o - (long)N_USERS * VEC]);
    float4 v1 = h4_to_f4(__ldcs(&x1[o]));
    float4 v2 = h4_to_f4(__ldg(&x2[o]));      // hot in L2 (gather table)
    float4 ov;
    ov.x = 0.25f * (v0.x + v1.x + v2.x + r.x);
    ov.y = 0.25f * (v0.y + v1.y + v2.y + r.y);
    ov.z = 0.25f * (v0.z + v1.z + v2.z + r.z);
    ov.w = 0.25f * (v0.w + v1.w + v2.w + r.w);
    __stcs(&out[o], ov);
}

extern "C" void kernel_launch(void* const* d_in, const int* in_sizes, int n_in,
                              void* d_out, int out_size) {
    const float* ue = (const float*)d_in[0];           // [N_USERS, 128]
    const float* ie = (const float*)d_in[1];           // [N_ITEMS, 128]
    const int*   ei = (const int*)d_in[2];             // [2, N_EDGES] int32
    const int* src = ei;
    const int* dst = ei + N_EDGES;
    float* out = (float*)d_out;                        // [N_NODES, 128] fp32

    uint2 *x0h, *x1, *x2;
    float *invdeg;
    int *deg, *rowptr, *cursor, *csr, *counter;
    cudaGetSymbolAddress((void**)&x0h, g_x0h);
    cudaGetSymbolAddress((void**)&x1, g_x1);
    cudaGetSymbolAddress((void**)&x2, g_x2);
    cudaGetSymbolAddress((void**)&invdeg, g_invdeg);
    cudaGetSymbolAddress((void**)&deg, g_deg);
    cudaGetSymbolAddress((void**)&rowptr, g_rowptr);
    cudaGetSymbolAddress((void**)&cursor, g_cursor);
    cudaGetSymbolAddress((void**)&csr, g_csr);
    cudaGetSymbolAddress((void**)&counter, g_counter);

    const int BT = 256;
    const long nvec = (long)N_NODES * VEC;             // 5,120,000

    // ---- CSR build (scan-free) + x0 fp16 conversion ----
    cudaMemsetAsync(deg, 0, N_NODES * sizeof(int));
    cudaMemsetAsync(counter, 0, sizeof(int));
    convhist_kernel<<<(int)((nvec + BT - 1) / BT), BT>>>(
        (const float4*)ue, (const float4*)ie, x0h, dst, deg);
    assign_kernel<<<(N_NODES + BT - 1) / BT, BT>>>(deg, rowptr, cursor,
                                                   invdeg, counter);
    permute_kernel<<<(N_EDGES + BT - 1) / BT, BT>>>(src, dst, cursor, csr);

    // ---- 3 propagation layers (warp per node); layer1 is launch #4 -> ncu ----
    const int blocks = (N_NODES * 32 + BT - 1) / BT;
    layer_kernel<<<blocks, BT>>>(rowptr, deg, csr, invdeg, x0h, x1);
    layer_kernel<<<blocks, BT>>>(rowptr, deg, csr, invdeg, x1, x2);
    layer3_kernel<<<blocks, BT>>>(rowptr, deg, csr, invdeg,
                                  (const float4*)ue, (const float4*)ie,
                                  x1, x2, (float4*)out);
}

// round 9
// speedup vs baseline: 1.4437x; 1.4437x over previous
#include <cuda_runtime.h>
#include <cuda_fp16.h>
#include <cstdint>

#define N_USERS 100000
#define N_ITEMS 60000
#define N_NODES (N_USERS + N_ITEMS)
#define EMB_DIM 128
#define VEC (EMB_DIM / 4)        // 32 chunks/row: float4 (fp32) or uint2 (fp16x4)
#define N_EDGES 1500000

// Scratch (__device__ globals per allocation-free rule)
__device__ uint2 g_x0h[(size_t)N_NODES * VEC];
__device__ uint2 g_x1[(size_t)N_NODES * VEC];
__device__ uint2 g_x2[(size_t)N_NODES * VEC];
__device__ float g_invdeg[N_NODES];
__device__ int   g_deg[N_NODES];
__device__ int   g_rowptr[N_NODES];
__device__ int   g_cursor[N_NODES];
__device__ int   g_csr[N_EDGES];
__device__ int   g_counter[1];

// ---------------------------------------------------------------------------
__device__ __forceinline__ float4 h4_to_f4(uint2 u) {
    float2 lo = __half22float2(*reinterpret_cast<__half2*>(&u.x));
    float2 hi = __half22float2(*reinterpret_cast<__half2*>(&u.y));
    float4 r; r.x = lo.x; r.y = lo.y; r.z = hi.x; r.w = hi.y;
    return r;
}
__device__ __forceinline__ uint2 f4_to_h4(float4 v) {
    __half2 lo = __floats2half2_rn(v.x, v.y);
    __half2 hi = __floats2half2_rn(v.z, v.w);
    uint2 u;
    u.x = *reinterpret_cast<uint32_t*>(&lo);
    u.y = *reinterpret_cast<uint32_t*>(&hi);
    return u;
}
__device__ __forceinline__ __half2 h2(uint32_t b) {
    return *reinterpret_cast<__half2*>(&b);
}

// 1) fused: convert concat(ue,ie) fp32->fp16 table  +  dst degree histogram
__global__ void convhist_kernel(const float4* __restrict__ ue,
                                const float4* __restrict__ ie,
                                uint2* __restrict__ x0h,
                                const int* __restrict__ dst,
                                int* __restrict__ deg) {
    long i = (long)blockIdx.x * blockDim.x + threadIdx.x;
    const long total = (long)N_NODES * VEC;        // 5,120,000
    if (i < total) {
        const long user_lim = (long)N_USERS * VEC;
        float4 v = (i < user_lim) ? __ldcs(&ue[i]) : __ldcs(&ie[i - user_lim]);
        __stcs(&x0h[i], f4_to_h4(v));
    }
    if (i < N_EDGES) atomicAdd(&deg[dst[(int)i]], 1);
}

// 2) segment assignment via global cursor (replaces prefix scan) + invdeg
__global__ void assign_kernel(const int* __restrict__ deg,
                              int* __restrict__ rowptr,
                              int* __restrict__ cursor,
                              float* __restrict__ invdeg,
                              int* __restrict__ counter) {
    int v = blockIdx.x * blockDim.x + threadIdx.x;
    if (v >= N_NODES) return;
    int d = deg[v];
    int beg = (d > 0) ? atomicAdd(counter, d) : 0;
    rowptr[v] = beg;
    cursor[v] = beg;
    invdeg[v] = (d > 0) ? (1.0f / (float)d) : 0.0f;
}

// 3) bin edges by dst into the assigned segments
__global__ void permute_kernel(const int* __restrict__ src,
                               const int* __restrict__ dst,
                               int* __restrict__ cursor,
                               int* __restrict__ csr) {
    int e = blockIdx.x * blockDim.x + threadIdx.x;
    if (e < N_EDGES) {
        int pos = atomicAdd(&cursor[dst[e]], 1);
        csr[pos] = src[e];
    }
}

// ---------------------------------------------------------------------------
// Warp-per-node mean over an fp16 table.
// 8-edge unroll; each 4-edge group is reduced with a depth-2 HADD2 tree in
// fp16 (inputs are exact fp16; <=2 fp16 adds per element), then converted
// once and accumulated in fp32. Cuts mainloop issue count ~1.8x vs
// convert-everything-first.
__device__ __forceinline__ float4 row_mean_h(const int* __restrict__ rowptr,
                                             const int* __restrict__ deg,
                                             const int* __restrict__ csr,
                                             const float* __restrict__ invdeg,
                                             const uint2* __restrict__ xin,
                                             int w, int lane) {
    int beg = __ldg(&rowptr[w]);
    int end = beg + __ldg(&deg[w]);
    float2 aLo = {0.f, 0.f}, aHi = {0.f, 0.f};   // group-A accumulator
    float2 bLo = {0.f, 0.f}, bHi = {0.f, 0.f};   // group-B accumulator
    int i = beg;
    for (; i + 7 < end; i += 8) {
        int s0 = csr[i],   s1 = csr[i+1], s2 = csr[i+2], s3 = csr[i+3];
        int s4 = csr[i+4], s5 = csr[i+5], s6 = csr[i+6], s7 = csr[i+7];
        uint2 u0 = __ldg(&xin[(long)s0 * VEC + lane]);
        uint2 u1 = __ldg(&xin[(long)s1 * VEC + lane]);
        uint2 u2 = __ldg(&xin[(long)s2 * VEC + lane]);
        uint2 u3 = __ldg(&xin[(long)s3 * VEC + lane]);
        uint2 u4 = __ldg(&xin[(long)s4 * VEC + lane]);
        uint2 u5 = __ldg(&xin[(long)s5 * VEC + lane]);
        uint2 u6 = __ldg(&xin[(long)s6 * VEC + lane]);
        uint2 u7 = __ldg(&xin[(long)s7 * VEC + lane]);
        // group A = edges 0..3, depth-2 fp16 tree per half2 chunk
        __half2 aL = __hadd2(__hadd2(h2(u0.x), h2(u1.x)),
                             __hadd2(h2(u2.x), h2(u3.x)));
        __half2 aH = __hadd2(__hadd2(h2(u0.y), h2(u1.y)),
                             __hadd2(h2(u2.y), h2(u3.y)));
        // group B = edges 4..7
        __half2 bL = __hadd2(__hadd2(h2(u4.x), h2(u5.x)),
                             __hadd2(h2(u6.x), h2(u7.x)));
        __half2 bH = __hadd2(__hadd2(h2(u4.y), h2(u5.y)),
                             __hadd2(h2(u6.y), h2(u7.y)));
        float2 f;
        f = __half22float2(aL); aLo.x += f.x; aLo.y += f.y;
        f = __half22float2(aH); aHi.x += f.x; aHi.y += f.y;
        f = __half22float2(bL); bLo.x += f.x; bLo.y += f.y;
        f = __half22float2(bH); bHi.x += f.x; bHi.y += f.y;
    }
    for (; i + 3 < end; i += 4) {
        int s0 = csr[i], s1 = csr[i+1], s2 = csr[i+2], s3 = csr[i+3];
        uint2 u0 = __ldg(&xin[(long)s0 * VEC + lane]);
        uint2 u1 = __ldg(&xin[(long)s1 * VEC + lane]);
        uint2 u2 = __ldg(&xin[(long)s2 * VEC + lane]);
        uint2 u3 = __ldg(&xin[(long)s3 * VEC + lane]);
        __half2 aL = __hadd2(__hadd2(h2(u0.x), h2(u1.x)),
                             __hadd2(h2(u2.x), h2(u3.x)));
        __half2 aH = __hadd2(__hadd2(h2(u0.y), h2(u1.y)),
                             __hadd2(h2(u2.y), h2(u3.y)));
        float2 f;
        f = __half22float2(aL); aLo.x += f.x; aLo.y += f.y;
        f = __half22float2(aH); aHi.x += f.x; aHi.y += f.y;
    }
    for (; i < end; ++i) {               // <=3 remainders in plain fp32
        int s = csr[i];
        float4 v = h4_to_f4(__ldg(&xin[(long)s * VEC + lane]));
        aLo.x += v.x; aLo.y += v.y; aHi.x += v.z; aHi.y += v.w;
    }
    float sc = __ldg(&invdeg[w]);
    float4 r;
    r.x = (aLo.x + bLo.x) * sc;
    r.y = (aLo.y + bLo.y) * sc;
    r.z = (aHi.x + bHi.x) * sc;
    r.w = (aHi.y + bHi.y) * sc;
    return r;
}

// Layers 1 & 2: xout (fp16) = A~ @ xin (fp16)
__global__ void __launch_bounds__(256)
layer_kernel(const int* __restrict__ rowptr, const int* __restrict__ deg,
             const int* __restrict__ csr, const float* __restrict__ invdeg,
             const uint2* __restrict__ xin, uint2* __restrict__ xout) {
    int w = (blockIdx.x * blockDim.x + threadIdx.x) >> 5;
    int lane = threadIdx.x & 31;
    if (w >= N_NODES) return;
    float4 r = row_mean_h(rowptr, deg, csr, invdeg, xin, w, lane);
    xout[(long)w * VEC + lane] = f4_to_h4(r);
}

// Layer 3 fused finale: r = A~ @ x2 (regs only); out = 0.25*(x0_fp32+x1+x2+r)
__global__ void __launch_bounds__(256)
layer3_kernel(const int* __restrict__ rowptr, const int* __restrict__ deg,
              const int* __restrict__ csr, const float* __restrict__ invdeg,
              const float4* __restrict__ ue, const float4* __restrict__ ie,
              const uint2* __restrict__ x1, const uint2* __restrict__ x2,
              float4* __restrict__ out) {
    int w = (blockIdx.x * blockDim.x + threadIdx.x) >> 5;
    int lane = threadIdx.x & 31;
    if (w >= N_NODES) return;
    float4 r = row_mean_h(rowptr, deg, csr, invdeg, x2, w, lane);
    long o = (long)w * VEC + lane;
    float4 v0 = (w < N_USERS) ? __ldcs(&ue[o]) : __ldcs(&ie[o - (long)N_USERS * VEC]);
    float4 v1 = h4_to_f4(__ldcs(&x1[o]));
    float4 v2 = h4_to_f4(__ldg(&x2[o]));      // hot in L2 (gather table)
    float4 ov;
    ov.x = 0.25f * (v0.x + v1.x + v2.x + r.x);
    ov.y = 0.25f * (v0.y + v1.y + v2.y + r.y);
    ov.z = 0.25f * (v0.z + v1.z + v2.z + r.z);
    ov.w = 0.25f * (v0.w + v1.w + v2.w + r.w);
    __stcs(&out[o], ov);
}

extern "C" void kernel_launch(void* const* d_in, const int* in_sizes, int n_in,
                              void* d_out, int out_size) {
    const float* ue = (const float*)d_in[0];           // [N_USERS, 128]
    const float* ie = (const float*)d_in[1];           // [N_ITEMS, 128]
    const int*   ei = (const int*)d_in[2];             // [2, N_EDGES] int32
    const int* src = ei;
    const int* dst = ei + N_EDGES;
    float* out = (float*)d_out;                        // [N_NODES, 128] fp32

    uint2 *x0h, *x1, *x2;
    float *invdeg;
    int *deg, *rowptr, *cursor, *csr, *counter;
    cudaGetSymbolAddress((void**)&x0h, g_x0h);
    cudaGetSymbolAddress((void**)&x1, g_x1);
    cudaGetSymbolAddress((void**)&x2, g_x2);
    cudaGetSymbolAddress((void**)&invdeg, g_invdeg);
    cudaGetSymbolAddress((void**)&deg, g_deg);
    cudaGetSymbolAddress((void**)&rowptr, g_rowptr);
    cudaGetSymbolAddress((void**)&cursor, g_cursor);
    cudaGetSymbolAddress((void**)&csr, g_csr);
    cudaGetSymbolAddress((void**)&counter, g_counter);

    const int BT = 256;
    const long nvec = (long)N_NODES * VEC;             // 5,120,000

    // ---- CSR build (scan-free) + x0 fp16 conversion ----
    cudaMemsetAsync(deg, 0, N_NODES * sizeof(int));
    cudaMemsetAsync(counter, 0, sizeof(int));
    convhist_kernel<<<(int)((nvec + BT - 1) / BT), BT>>>(
        (const float4*)ue, (const float4*)ie, x0h, dst, deg);
    assign_kernel<<<(N_NODES + BT - 1) / BT, BT>>>(deg, rowptr, cursor,
                                                   invdeg, counter);
    permute_kernel<<<(N_EDGES + BT - 1) / BT, BT>>>(src, dst, cursor, csr);

    // ---- 3 propagation layers (warp per node); layer1 is launch #4 -> ncu ----
    const int blocks = (N_NODES * 32 + BT - 1) / BT;
    layer_kernel<<<blocks, BT>>>(rowptr, deg, csr, invdeg, x0h, x1);
    layer_kernel<<<blocks, BT>>>(rowptr, deg, csr, invdeg, x1, x2);
    layer3_kernel<<<blocks, BT>>>(rowptr, deg, csr, invdeg,
                                  (const float4*)ue, (const float4*)ie,
                                  x1, x2, (float4*)out);
}